// round 6
// baseline (speedup 1.0000x reference)
#include <cuda_runtime.h>
#include <math.h>

#define NE     200000
#define NI     100000
#define DIM    64
#define NEDGE  1500000
#define KEDGE  256
#define KITEM  100
#define SCALE  0.08838834764831845f   // 1/(2*sqrt(32))

#define CAND_MAX 2048
#define NBINS    8192                 // 13-bit key prefix
#define BIN_SHIFT 19

// persistent kernel: 592 blocks = 148 SM x 4 (co-resident via launch_bounds)
#define TE_BLOCKS 512
#define TI_BLOCKS 80
#define NB_TOTAL  (TE_BLOCKS + TI_BLOCKS)
#define TE_STRIDE (TE_BLOCKS * 256)           // 131072
#define TE_ITEMS  12                          // 12*131072 >= NEDGE
#define TI_STRIDE (TI_BLOCKS * 256)           // 20480
#define TI_ITEMS  5                           // 5*20480 >= NI
#define NWARPS    (NB_TOTAL * 8)              // 4736 warps, 2 edges each per iter

// ---------------- scratch ----------------
__device__ float    g_proj[NE * DIM];
__device__ float    g_ex[NEDGE];
__device__ float    g_dd[2 * NE];             // [denom, deg]
__device__ float    g_sumnode[NE];

__device__ unsigned g_bins_e[NBINS];
__device__ unsigned g_bins_i[NBINS];
__device__ unsigned g_kth_e, g_kth_i;
__device__ int      g_cnt[2];
__device__ unsigned long long g_cand_e[CAND_MAX];
__device__ unsigned long long g_cand_i[CAND_MAX];

__device__ unsigned g_bar_cnt;                // zero-init, self-resetting
__device__ volatile unsigned g_bar_gen;

// ---------------- helpers ----------------
__device__ __forceinline__ unsigned fkey(float f) {
    unsigned u = __float_as_uint(f);
    return (u & 0x80000000u) ? ~u : (u | 0x80000000u);
}
__device__ __forceinline__ float keyf(unsigned k) {
    unsigned u = (k & 0x80000000u) ? (k & 0x7FFFFFFFu) : ~k;
    return __uint_as_float(u);
}

#define PACK2(out, lo, hi) \
    asm("mov.b64 %0, {%1, %2};" : "=l"(out) : "f"(lo), "f"(hi))
#define UNPACK2(lo, hi, in) \
    asm("mov.b64 {%0, %1}, %2;" : "=f"(lo), "=f"(hi) : "l"(in))
#define FMA2(d, a, b, c) \
    asm("fma.rn.f32x2 %0, %1, %2, %3;" : "=l"(d) : "l"(a), "l"(b), "l"(c))

__device__ __forceinline__ void grid_sync() {
    __threadfence();
    __syncthreads();
    if (threadIdx.x == 0) {
        unsigned gen = g_bar_gen;
        if (atomicAdd(&g_bar_cnt, 1u) == gridDim.x - 1) {
            g_bar_cnt = 0u;
            __threadfence();
            g_bar_gen = gen + 1u;
        } else {
            while (g_bar_gen == gen) { __nanosleep(64); }
        }
        __threadfence();
    }
    __syncthreads();
}

// one block: find 13-bit prefix bin of the Kth-largest key
__device__ void select13(volatile unsigned* bins, int K, unsigned* out_kth) {
    __shared__ unsigned s_sum[256];
    __shared__ unsigned s_kth;
    int t = threadIdx.x;
    unsigned sum = 0;
    #pragma unroll
    for (int i = 0; i < 32; i++) sum += bins[t * 32 + i];
    s_sum[t] = sum;
    __syncthreads();
    #pragma unroll
    for (int off = 1; off < 256; off <<= 1) {
        unsigned v = s_sum[t];
        if (t + off < 256) v += s_sum[t + off];
        __syncthreads();
        s_sum[t] = v;
        __syncthreads();
    }
    unsigned incl = s_sum[t];
    unsigned above = incl - sum;
    if ((int)above < K && K <= (int)incl) {
        unsigned run = above;
        for (int i = 31; i >= 0; i--) {
            run += bins[t * 32 + i];
            if ((int)run >= K) { s_kth = (unsigned)(t * 32 + i) << BIN_SHIFT; break; }
        }
    }
    __syncthreads();
    if (t == 0) *out_kth = s_kth;
}

// one block: bitonic-sort candidates (value desc, idx asc), emit top K
__device__ void sort_emit(unsigned long long* s, unsigned long long* cand,
                          volatile int* cntp,
                          float* __restrict__ outV, float* __restrict__ outI, int K) {
    int cnt = *cntp;
    if (cnt > CAND_MAX) cnt = CAND_MAX;
    int n2 = 1; while (n2 < cnt) n2 <<= 1;
    for (int i = threadIdx.x; i < n2; i += 256)
        s[i] = (i < cnt) ? ((volatile unsigned long long*)cand)[i]
                         : 0xFFFFFFFFFFFFFFFFull;
    __syncthreads();
    for (int k = 2; k <= n2; k <<= 1) {
        for (int j = k >> 1; j > 0; j >>= 1) {
            for (int i = threadIdx.x; i < n2; i += 256) {
                int p = i ^ j;
                if (p > i) {
                    bool up = ((i & k) == 0);
                    unsigned long long a = s[i], b = s[p];
                    if ((a > b) == up) { s[i] = b; s[p] = a; }
                }
            }
            __syncthreads();
        }
    }
    for (int t = threadIdx.x; t < K; t += 256) {
        unsigned long long cc = s[t];
        outV[t] = keyf(~(unsigned)(cc >> 32));
        outI[t] = (float)(unsigned)(cc & 0xFFFFFFFFu);
    }
}

// ---------------- 1) projection, packed f32x2 FMA (+ fused init) ------------
__global__ void k_proj(const float* __restrict__ emb, const float* __restrict__ W) {
    __shared__ float sE[64 * 68];
    __shared__ float sW[64 * 64];
    int tid = threadIdx.x;               // 128
    int base = blockIdx.x * 64 * DIM;
    int eb = blockIdx.x * 64;

    g_dd[2 * eb + tid] = 0.0f;
    if (tid < 64) g_sumnode[eb + tid] = 0.0f;
    if (blockIdx.x < 64)        g_bins_e[blockIdx.x * 128 + tid] = 0u;
    else if (blockIdx.x < 128)  g_bins_i[(blockIdx.x - 64) * 128 + tid] = 0u;
    else if (blockIdx.x == 128 && tid < 2) g_cnt[tid] = 0;

    const float4* ev = (const float4*)(emb + base);
    const float4* wv = (const float4*)W;
    #pragma unroll
    for (int i = tid; i < 1024; i += 128) {
        int r = i >> 4, c = i & 15;
        *(float4*)&sE[r * 68 + c * 4] = ev[i];
        ((float4*)sW)[i] = wv[i];
    }
    __syncthreads();

    int tr = tid >> 4;
    int tc = tid & 15;

    unsigned long long a01[8], a23[8];
    #pragma unroll
    for (int i = 0; i < 8; i++) { a01[i] = 0ull; a23[i] = 0ull; }

    #pragma unroll
    for (int d4 = 0; d4 < 16; d4++) {
        unsigned long long w01[4], w23[4];
        #pragma unroll
        for (int j = 0; j < 4; j++) {
            float4 w = *(const float4*)&sW[(d4 * 4 + j) * 64 + tc * 4];
            PACK2(w01[j], w.x, w.y);
            PACK2(w23[j], w.z, w.w);
        }
        #pragma unroll
        for (int i = 0; i < 8; i++) {
            float4 e = *(const float4*)&sE[(tr * 8 + i) * 68 + d4 * 4];
            unsigned long long ee;
            PACK2(ee, e.x, e.x); FMA2(a01[i], ee, w01[0], a01[i]); FMA2(a23[i], ee, w23[0], a23[i]);
            PACK2(ee, e.y, e.y); FMA2(a01[i], ee, w01[1], a01[i]); FMA2(a23[i], ee, w23[1], a23[i]);
            PACK2(ee, e.z, e.z); FMA2(a01[i], ee, w01[2], a01[i]); FMA2(a23[i], ee, w23[2], a23[i]);
            PACK2(ee, e.w, e.w); FMA2(a01[i], ee, w01[3], a01[i]); FMA2(a23[i], ee, w23[3], a23[i]);
        }
    }
    #pragma unroll
    for (int i = 0; i < 8; i++) {
        float4 o;
        UNPACK2(o.x, o.y, a01[i]);
        UNPACK2(o.z, o.w, a23[i]);
        *(float4*)&g_proj[base + (tr * 8 + i) * 64 + tc * 4] = o;
    }
}

// accurate-cheap -log(u): series near 1 (MUFU abs error would wreck the top
// gumbel candidates where x = -log u ~ 1e-6), __logf elsewhere
__device__ __forceinline__ float neglog(float u) {
    float t = u - 1.0f;
    float p = fmaf(t, -0.16666667f, 0.2f);
    p = fmaf(t, p, -0.25f);
    p = fmaf(t, p, 0.33333333f);
    p = fmaf(t, p, -0.5f);
    p = fmaf(t, p, 1.0f);
    float ser = -t * p;
    float fast = -__logf(u);
    return (u > 0.84f) ? ser : fast;
}

// warp-aggregated smem histogram add (keys are highly concentrated)
__device__ __forceinline__ void hist_add(unsigned* sh, unsigned bin) {
    unsigned m = __match_any_sync(0xffffffffu, bin);
    int leader = __ffs(m) - 1;
    if ((int)(threadIdx.x & 31) == leader) atomicAdd(&sh[bin], __popc(m));
}

// process one edge with a half-warp (16 lanes)
__device__ __forceinline__ void edge_one(int e, int sub,
                                         const int* __restrict__ head,
                                         const int* __restrict__ tail,
                                         const int* __restrict__ etype,
                                         const float* __restrict__ rel) {
    int h = __ldg(&head[e]);
    int t = __ldg(&tail[e]);
    int r = __ldg(&etype[e]) - 1;

    float4 q  = *(const float4*)&g_proj[((size_t)h << 6) + (sub << 2)];
    float4 kv = *(const float4*)&g_proj[((size_t)t << 6) + (sub << 2)];
    float4 rv = __ldg((const float4*)rel + ((size_t)r << 4) + sub);

    float s = q.x * kv.x * rv.x + q.y * kv.y * rv.y
            + q.z * kv.z * rv.z + q.w * kv.w * rv.w;
    s += __shfl_xor_sync(0xffffffffu, s, 8);
    s += __shfl_xor_sync(0xffffffffu, s, 4);
    s += __shfl_xor_sync(0xffffffffu, s, 2);
    s += __shfl_xor_sync(0xffffffffu, s, 1);

    float lg = s * SCALE;
    if (sub == 0) { g_ex[e] = __expf(lg); atomicAdd(&g_dd[2 * h], __expf(lg)); }
    else if (sub == 1) atomicAdd(&g_dd[2 * h + 1], 1.0f);
    else if (sub == 2) atomicAdd(&g_sumnode[h], lg);
    else if (sub == 3) atomicAdd(&g_sumnode[t], lg);
}

// ---------------- 2) fused: edges + score + topk, one persistent kernel -----
__global__ void __launch_bounds__(256, 4)
k_main(const int* __restrict__ head, const int* __restrict__ tail,
       const int* __restrict__ etype, const float* __restrict__ rel,
       const float* __restrict__ noise,
       float* __restrict__ out,
       float* __restrict__ tkv, float* __restrict__ tki,
       float* __restrict__ itv, float* __restrict__ iti) {
    __shared__ unsigned long long s_buf[NBINS / 2];   // 32KB: hist, then sort
    unsigned* s_hist = (unsigned*)s_buf;
    unsigned key[TE_ITEMS];
    int tid = threadIdx.x;
    bool isE = blockIdx.x < TE_BLOCKS;

    #pragma unroll
    for (int i = 0; i < NBINS / 256; i++) s_hist[tid + i * 256] = 0u;

    // ---- phase 0: edge logits (grid-stride, warp-cooperative, 2 edges/warp) --
    {
        int warp_id = blockIdx.x * 8 + (tid >> 5);   // 0..NWARPS-1
        int lane = tid & 31;
        int half = lane >> 4;
        int sub  = lane & 15;
        // pairs: warp w handles pair indices w, w+NWARPS, ... ; edge = 2*pair+half
        #pragma unroll 2
        for (int pr = warp_id; pr < NEDGE / 2; pr += NWARPS)
            edge_one(2 * pr + half, sub, head, tail, etype, rel);
    }
    grid_sync();

    // ---- phase A: keys + warp-aggregated 13-bit smem hist ----
    if (isE) {
        int gtid = blockIdx.x * 256 + tid;
        #pragma unroll
        for (int i = 0; i < TE_ITEMS; i++) {
            int e = gtid + i * TE_STRIDE;
            unsigned k = 0u;
            if (e < NEDGE) {
                int h = __ldg(&head[e]);
                float2 dd = *(const float2*)&g_dd[2 * h];   // (denom, deg)
                float sc = __ldg(&g_ex[e]) * dd.y * __frcp_rn(dd.x);
                out[e] = sc;
                float x = neglog(__ldg(&noise[e]));          // -log(u)
                k = fkey(sc - __logf(x));                    // + gumbel
            }
            key[i] = k;
            hist_add(s_hist, k >> BIN_SHIFT);
        }
        __syncthreads();
        #pragma unroll
        for (int i = 0; i < NBINS / 256; i++) {
            unsigned c = s_hist[tid + i * 256];
            if (c) atomicAdd(&g_bins_e[tid + i * 256], c);
        }
    } else {
        int gtid = (blockIdx.x - TE_BLOCKS) * 256 + tid;
        #pragma unroll
        for (int i = 0; i < TI_ITEMS; i++) {
            int e = gtid + i * TI_STRIDE;
            unsigned k = (e < NI) ? fkey(g_sumnode[e]) : 0u;
            key[i] = k;
            hist_add(s_hist, k >> BIN_SHIFT);
        }
        __syncthreads();
        #pragma unroll
        for (int i = 0; i < NBINS / 256; i++) {
            unsigned c = s_hist[tid + i * 256];
            if (c) atomicAdd(&g_bins_i[tid + i * 256], c);
        }
    }
    grid_sync();

    // ---- phase B: threshold select ----
    if (blockIdx.x == 0)              select13(g_bins_e, KEDGE, &g_kth_e);
    else if (blockIdx.x == TE_BLOCKS) select13(g_bins_i, KITEM, &g_kth_i);
    grid_sync();

    // ---- phase C: collect candidates >= threshold ----
    if (isE) {
        unsigned kth = *(volatile unsigned*)&g_kth_e;
        int gtid = blockIdx.x * 256 + tid;
        #pragma unroll
        for (int i = 0; i < TE_ITEMS; i++) {
            unsigned k = key[i];
            if (k >= kth) {
                int p = atomicAdd(&g_cnt[0], 1);
                if (p < CAND_MAX)
                    g_cand_e[p] = (((unsigned long long)(~k)) << 32)
                                | (unsigned)(gtid + i * TE_STRIDE);
            }
        }
    } else {
        unsigned kth = *(volatile unsigned*)&g_kth_i;
        int gtid = (blockIdx.x - TE_BLOCKS) * 256 + tid;
        #pragma unroll
        for (int i = 0; i < TI_ITEMS; i++) {
            unsigned k = key[i];
            if (k >= kth) {
                int p = atomicAdd(&g_cnt[1], 1);
                if (p < CAND_MAX)
                    g_cand_i[p] = (((unsigned long long)(~k)) << 32)
                                | (unsigned)(gtid + i * TI_STRIDE);
            }
        }
    }
    grid_sync();

    // ---- phase D: sort + emit ----
    if (blockIdx.x == 0)
        sort_emit(s_buf, g_cand_e, &g_cnt[0], tkv, tki, KEDGE);
    else if (blockIdx.x == TE_BLOCKS)
        sort_emit(s_buf, g_cand_i, &g_cnt[1], itv, iti, KITEM);
}

// ---------------- host ----------------
extern "C" void kernel_launch(void* const* d_in, const int* in_sizes, int n_in,
                              void* d_out, int out_size) {
    const float* emb   = (const float*)d_in[0];
    const float* WQ    = (const float*)d_in[1];
    const float* rel   = (const float*)d_in[2];
    const float* noise = (const float*)d_in[3];
    const int*   eidx  = (const int*)d_in[4];
    const int*   etype = (const int*)d_in[5];
    const int* head = eidx;
    const int* tail = eidx + NEDGE;
    float* out = (float*)d_out;

    float* out_tkv = out + NEDGE;
    float* out_tki = out + NEDGE + KEDGE;
    float* out_itv = out + NEDGE + 2 * KEDGE;
    float* out_iti = out + NEDGE + 2 * KEDGE + KITEM;

    k_proj<<<NE / 64, 128>>>(emb, WQ);
    k_main<<<NB_TOTAL, 256>>>(head, tail, etype, rel, noise, out,
                              out_tkv, out_tki, out_itv, out_iti);
}

// round 7
// speedup vs baseline: 1.5651x; 1.5651x over previous
#include <cuda_runtime.h>
#include <math.h>

#define NE     200000
#define NI     100000
#define DIM    64
#define NEDGE  1500000
#define KEDGE  256
#define KITEM  100
#define SCALE  0.08838834764831845f   // 1/(2*sqrt(32))

#define CAND_MAX 2048
#define NBINS    8192                 // 13-bit key prefix
#define BIN_SHIFT 19

// topk persistent kernel: 592 blocks = 148 SM x 4 (co-resident)
#define TE_BLOCKS 512
#define TI_BLOCKS 80
#define NB_TOTAL  (TE_BLOCKS + TI_BLOCKS)
#define TE_STRIDE (TE_BLOCKS * 256)           // 131072
#define TE_ITEMS  12                          // 12*131072 >= NEDGE
#define TI_STRIDE (TI_BLOCKS * 256)           // 20480
#define TI_ITEMS  5                           // 5*20480 >= NI

// edge kernel: grid-stride, 8 edges per warp per step
#define EDGE_BLOCKS 1184                      // 148 * 8
#define EDGE_WARPS  (EDGE_BLOCKS * 8)         // 9472
#define EDGE_GROUPS (NEDGE / 8)               // 187500 groups of 8 edges

// ---------------- scratch ----------------
__device__ float    g_proj[NE * DIM];
__device__ float    g_ex[NEDGE];
__device__ float    g_dd[2 * NE];             // [denom, deg]
__device__ float    g_sumnode[NE];

__device__ unsigned g_bins_e[NBINS];
__device__ unsigned g_bins_i[NBINS];
__device__ unsigned g_kth_e, g_kth_i;
__device__ int      g_cnt[2];
__device__ unsigned long long g_cand_e[CAND_MAX];
__device__ unsigned long long g_cand_i[CAND_MAX];

__device__ unsigned g_bar_cnt;                // zero-init, self-resetting
__device__ volatile unsigned g_bar_gen;

// ---------------- helpers ----------------
__device__ __forceinline__ unsigned fkey(float f) {
    unsigned u = __float_as_uint(f);
    return (u & 0x80000000u) ? ~u : (u | 0x80000000u);
}
__device__ __forceinline__ float keyf(unsigned k) {
    unsigned u = (k & 0x80000000u) ? (k & 0x7FFFFFFFu) : ~k;
    return __uint_as_float(u);
}

#define PACK2(out, lo, hi) \
    asm("mov.b64 %0, {%1, %2};" : "=l"(out) : "f"(lo), "f"(hi))
#define UNPACK2(lo, hi, in) \
    asm("mov.b64 {%0, %1}, %2;" : "=f"(lo), "=f"(hi) : "l"(in))
#define FMA2(d, a, b, c) \
    asm("fma.rn.f32x2 %0, %1, %2, %3;" : "=l"(d) : "l"(a), "l"(b), "l"(c))

__device__ __forceinline__ void grid_sync() {
    __threadfence();
    __syncthreads();
    if (threadIdx.x == 0) {
        unsigned gen = g_bar_gen;
        if (atomicAdd(&g_bar_cnt, 1u) == gridDim.x - 1) {
            g_bar_cnt = 0u;
            __threadfence();
            g_bar_gen = gen + 1u;
        } else {
            while (g_bar_gen == gen) { __nanosleep(64); }
        }
        __threadfence();
    }
    __syncthreads();
}

// one block: find 13-bit prefix bin of the Kth-largest key
__device__ void select13(volatile unsigned* bins, int K, unsigned* out_kth) {
    __shared__ unsigned s_sum[256];
    __shared__ unsigned s_kth;
    int t = threadIdx.x;
    unsigned sum = 0;
    #pragma unroll
    for (int i = 0; i < 32; i++) sum += bins[t * 32 + i];
    s_sum[t] = sum;
    __syncthreads();
    #pragma unroll
    for (int off = 1; off < 256; off <<= 1) {
        unsigned v = s_sum[t];
        if (t + off < 256) v += s_sum[t + off];
        __syncthreads();
        s_sum[t] = v;
        __syncthreads();
    }
    unsigned incl = s_sum[t];
    unsigned above = incl - sum;
    if ((int)above < K && K <= (int)incl) {
        unsigned run = above;
        for (int i = 31; i >= 0; i--) {
            run += bins[t * 32 + i];
            if ((int)run >= K) { s_kth = (unsigned)(t * 32 + i) << BIN_SHIFT; break; }
        }
    }
    __syncthreads();
    if (t == 0) *out_kth = s_kth;
}

// one block: bitonic-sort candidates (value desc, idx asc), emit top K
__device__ void sort_emit(unsigned long long* s, unsigned long long* cand,
                          volatile int* cntp,
                          float* __restrict__ outV, float* __restrict__ outI, int K) {
    int cnt = *cntp;
    if (cnt > CAND_MAX) cnt = CAND_MAX;
    int n2 = 1; while (n2 < cnt) n2 <<= 1;
    for (int i = threadIdx.x; i < n2; i += 256)
        s[i] = (i < cnt) ? ((volatile unsigned long long*)cand)[i]
                         : 0xFFFFFFFFFFFFFFFFull;
    __syncthreads();
    for (int k = 2; k <= n2; k <<= 1) {
        for (int j = k >> 1; j > 0; j >>= 1) {
            for (int i = threadIdx.x; i < n2; i += 256) {
                int p = i ^ j;
                if (p > i) {
                    bool up = ((i & k) == 0);
                    unsigned long long a = s[i], b = s[p];
                    if ((a > b) == up) { s[i] = b; s[p] = a; }
                }
            }
            __syncthreads();
        }
    }
    for (int t = threadIdx.x; t < K; t += 256) {
        unsigned long long cc = s[t];
        outV[t] = keyf(~(unsigned)(cc >> 32));
        outI[t] = (float)(unsigned)(cc & 0xFFFFFFFFu);
    }
}

// ---------------- 1) projection, packed f32x2 FMA (+ fused init) ------------
__global__ void k_proj(const float* __restrict__ emb, const float* __restrict__ W) {
    __shared__ float sE[64 * 68];
    __shared__ float sW[64 * 64];
    int tid = threadIdx.x;               // 128
    int base = blockIdx.x * 64 * DIM;
    int eb = blockIdx.x * 64;

    g_dd[2 * eb + tid] = 0.0f;
    if (tid < 64) g_sumnode[eb + tid] = 0.0f;
    if (blockIdx.x < 64)        g_bins_e[blockIdx.x * 128 + tid] = 0u;
    else if (blockIdx.x < 128)  g_bins_i[(blockIdx.x - 64) * 128 + tid] = 0u;
    else if (blockIdx.x == 128 && tid < 2) g_cnt[tid] = 0;

    const float4* ev = (const float4*)(emb + base);
    const float4* wv = (const float4*)W;
    #pragma unroll
    for (int i = tid; i < 1024; i += 128) {
        int r = i >> 4, c = i & 15;
        *(float4*)&sE[r * 68 + c * 4] = ev[i];
        ((float4*)sW)[i] = wv[i];
    }
    __syncthreads();

    int tr = tid >> 4;
    int tc = tid & 15;

    unsigned long long a01[8], a23[8];
    #pragma unroll
    for (int i = 0; i < 8; i++) { a01[i] = 0ull; a23[i] = 0ull; }

    #pragma unroll
    for (int d4 = 0; d4 < 16; d4++) {
        unsigned long long w01[4], w23[4];
        #pragma unroll
        for (int j = 0; j < 4; j++) {
            float4 w = *(const float4*)&sW[(d4 * 4 + j) * 64 + tc * 4];
            PACK2(w01[j], w.x, w.y);
            PACK2(w23[j], w.z, w.w);
        }
        #pragma unroll
        for (int i = 0; i < 8; i++) {
            float4 e = *(const float4*)&sE[(tr * 8 + i) * 68 + d4 * 4];
            unsigned long long ee;
            PACK2(ee, e.x, e.x); FMA2(a01[i], ee, w01[0], a01[i]); FMA2(a23[i], ee, w23[0], a23[i]);
            PACK2(ee, e.y, e.y); FMA2(a01[i], ee, w01[1], a01[i]); FMA2(a23[i], ee, w23[1], a23[i]);
            PACK2(ee, e.z, e.z); FMA2(a01[i], ee, w01[2], a01[i]); FMA2(a23[i], ee, w23[2], a23[i]);
            PACK2(ee, e.w, e.w); FMA2(a01[i], ee, w01[3], a01[i]); FMA2(a23[i], ee, w23[3], a23[i]);
        }
    }
    #pragma unroll
    for (int i = 0; i < 8; i++) {
        float4 o;
        UNPACK2(o.x, o.y, a01[i]);
        UNPACK2(o.z, o.w, a23[i]);
        *(float4*)&g_proj[base + (tr * 8 + i) * 64 + tc * 4] = o;
    }
}

// ---------------- 2) edge kernel: 4 lanes/edge, 8 edges/warp, grid-stride ---
// High MLP: 8 independent gather streams per warp step (x2 with unroll),
// 2-deep shfl reduce, no smem -> high occupancy.
__device__ __forceinline__ void edge8(int grp,
                                      const int* __restrict__ head,
                                      const int* __restrict__ tail,
                                      const int* __restrict__ etype,
                                      const float* __restrict__ rel,
                                      int g, int sub) {
    int e = grp * 8 + g;
    int h = __ldg(&head[e]);
    int t = __ldg(&tail[e]);
    int r = __ldg(&etype[e]) - 1;

    const float4* Q = (const float4*)&g_proj[(size_t)h << 6];
    const float4* K = (const float4*)&g_proj[(size_t)t << 6];
    const float4* R = (const float4*)rel + ((size_t)r << 4);

    float s = 0.0f;
    #pragma unroll
    for (int j = 0; j < 4; j++) {
        float4 q = __ldg(Q + sub + 4 * j);
        float4 k = __ldg(K + sub + 4 * j);
        float4 v = __ldg(R + sub + 4 * j);
        s += q.x * k.x * v.x + q.y * k.y * v.y + q.z * k.z * v.z + q.w * k.w * v.w;
    }
    s += __shfl_xor_sync(0xffffffffu, s, 1);
    s += __shfl_xor_sync(0xffffffffu, s, 2);

    float lg = s * SCALE;
    if (sub == 0) {
        float ex = __expf(lg);
        g_ex[e] = ex;
        atomicAdd(&g_dd[2 * h], ex);
        atomicAdd(&g_sumnode[h], lg);
    } else if (sub == 1) {
        atomicAdd(&g_dd[2 * h + 1], 1.0f);
        atomicAdd(&g_sumnode[t], lg);
    }
}

__global__ void __launch_bounds__(256)
k_edge(const int* __restrict__ head, const int* __restrict__ tail,
       const int* __restrict__ etype, const float* __restrict__ rel) {
    int warp = blockIdx.x * 8 + (threadIdx.x >> 5);
    int lane = threadIdx.x & 31;
    int g = lane >> 2;        // edge slot 0..7
    int sub = lane & 3;       // quarter-row 0..3

    int grp = warp;
    // EDGE_GROUPS = 187500; warps 9472 -> 19 full strides + remainder
    #pragma unroll 2
    for (; grp + EDGE_WARPS < EDGE_GROUPS; grp += EDGE_WARPS)
        edge8(grp, head, tail, etype, rel, g, sub);
    if (grp < EDGE_GROUPS)
        edge8(grp, head, tail, etype, rel, g, sub);
}

// accurate-cheap -log(u): series near 1, __logf elsewhere
__device__ __forceinline__ float neglog(float u) {
    float t = u - 1.0f;
    float p = fmaf(t, -0.16666667f, 0.2f);
    p = fmaf(t, p, -0.25f);
    p = fmaf(t, p, 0.33333333f);
    p = fmaf(t, p, -0.5f);
    p = fmaf(t, p, 1.0f);
    float ser = -t * p;
    float fast = -__logf(u);
    return (u > 0.84f) ? ser : fast;
}

// warp-aggregated smem histogram add
__device__ __forceinline__ void hist_add(unsigned* sh, unsigned bin) {
    unsigned m = __match_any_sync(0xffffffffu, bin);
    int leader = __ffs(m) - 1;
    if ((int)(threadIdx.x & 31) == leader) atomicAdd(&sh[bin], __popc(m));
}

// ---------------- 3) fused topk (edges + items), 3 grid syncs ---------------
__global__ void __launch_bounds__(256, 4)
k_topk(const int* __restrict__ head, const float* __restrict__ noise,
       float* __restrict__ out,
       float* __restrict__ tkv, float* __restrict__ tki,
       float* __restrict__ itv, float* __restrict__ iti) {
    __shared__ unsigned long long s_buf[NBINS / 2];   // 32KB: hist, then sort
    unsigned* s_hist = (unsigned*)s_buf;
    unsigned key[TE_ITEMS];
    int tid = threadIdx.x;
    bool isE = blockIdx.x < TE_BLOCKS;

    #pragma unroll
    for (int i = 0; i < NBINS / 256; i++) s_hist[tid + i * 256] = 0u;
    __syncthreads();

    // ---- phase A: keys + warp-aggregated 13-bit smem hist ----
    if (isE) {
        int gtid = blockIdx.x * 256 + tid;
        #pragma unroll
        for (int i = 0; i < TE_ITEMS; i++) {
            int e = gtid + i * TE_STRIDE;
            unsigned k = 0u;
            if (e < NEDGE) {
                int h = __ldg(&head[e]);
                float2 dd = *(const float2*)&g_dd[2 * h];   // (denom, deg)
                float sc = __ldg(&g_ex[e]) * dd.y * __frcp_rn(dd.x);
                out[e] = sc;
                float x = neglog(__ldg(&noise[e]));          // -log(u)
                k = fkey(sc - __logf(x));                    // + gumbel
            }
            key[i] = k;
            hist_add(s_hist, k >> BIN_SHIFT);
        }
        __syncthreads();
        #pragma unroll
        for (int i = 0; i < NBINS / 256; i++) {
            unsigned c = s_hist[tid + i * 256];
            if (c) atomicAdd(&g_bins_e[tid + i * 256], c);
        }
    } else {
        int gtid = (blockIdx.x - TE_BLOCKS) * 256 + tid;
        #pragma unroll
        for (int i = 0; i < TI_ITEMS; i++) {
            int e = gtid + i * TI_STRIDE;
            unsigned k = (e < NI) ? fkey(g_sumnode[e]) : 0u;
            key[i] = k;
            hist_add(s_hist, k >> BIN_SHIFT);
        }
        __syncthreads();
        #pragma unroll
        for (int i = 0; i < NBINS / 256; i++) {
            unsigned c = s_hist[tid + i * 256];
            if (c) atomicAdd(&g_bins_i[tid + i * 256], c);
        }
    }
    grid_sync();

    // ---- phase B: threshold select ----
    if (blockIdx.x == 0)              select13(g_bins_e, KEDGE, &g_kth_e);
    else if (blockIdx.x == TE_BLOCKS) select13(g_bins_i, KITEM, &g_kth_i);
    grid_sync();

    // ---- phase C: collect candidates >= threshold ----
    if (isE) {
        unsigned kth = *(volatile unsigned*)&g_kth_e;
        int gtid = blockIdx.x * 256 + tid;
        #pragma unroll
        for (int i = 0; i < TE_ITEMS; i++) {
            unsigned k = key[i];
            if (k >= kth) {
                int p = atomicAdd(&g_cnt[0], 1);
                if (p < CAND_MAX)
                    g_cand_e[p] = (((unsigned long long)(~k)) << 32)
                                | (unsigned)(gtid + i * TE_STRIDE);
            }
        }
    } else {
        unsigned kth = *(volatile unsigned*)&g_kth_i;
        int gtid = (blockIdx.x - TE_BLOCKS) * 256 + tid;
        #pragma unroll
        for (int i = 0; i < TI_ITEMS; i++) {
            unsigned k = key[i];
            if (k >= kth) {
                int p = atomicAdd(&g_cnt[1], 1);
                if (p < CAND_MAX)
                    g_cand_i[p] = (((unsigned long long)(~k)) << 32)
                                | (unsigned)(gtid + i * TI_STRIDE);
            }
        }
    }
    grid_sync();

    // ---- phase D: sort + emit ----
    if (blockIdx.x == 0)
        sort_emit(s_buf, g_cand_e, &g_cnt[0], tkv, tki, KEDGE);
    else if (blockIdx.x == TE_BLOCKS)
        sort_emit(s_buf, g_cand_i, &g_cnt[1], itv, iti, KITEM);
}

// ---------------- host ----------------
extern "C" void kernel_launch(void* const* d_in, const int* in_sizes, int n_in,
                              void* d_out, int out_size) {
    const float* emb   = (const float*)d_in[0];
    const float* WQ    = (const float*)d_in[1];
    const float* rel   = (const float*)d_in[2];
    const float* noise = (const float*)d_in[3];
    const int*   eidx  = (const int*)d_in[4];
    const int*   etype = (const int*)d_in[5];
    const int* head = eidx;
    const int* tail = eidx + NEDGE;
    float* out = (float*)d_out;

    float* out_tkv = out + NEDGE;
    float* out_tki = out + NEDGE + KEDGE;
    float* out_itv = out + NEDGE + 2 * KEDGE;
    float* out_iti = out + NEDGE + 2 * KEDGE + KITEM;

    k_proj<<<NE / 64, 128>>>(emb, WQ);
    k_edge<<<EDGE_BLOCKS, 256>>>(head, tail, etype, rel);
    k_topk<<<NB_TOTAL, 256>>>(head, noise, out, out_tkv, out_tki, out_itv, out_iti);
}